// round 10
// baseline (speedup 1.0000x reference)
#include <cuda_runtime.h>
#include <cuda_bf16.h>
#include <cstdint>
#include <math.h>

// Problem constants
#define BB 2048
#define DD 4096
#define PP 64
#define EE 8
#define KK 64
#define TWO_C 128

#define WROW 72          // padded row stride in bf16 (144 B): conflict-free ldmatrix
#define WROWB 144
#define BUFB (PP * WROWB)     // one B-tile buffer: 9216 B

#define RBLK (BB / 2)    // router blocks: 2 b's per block, 4 warps per b
#define TPB 4            // expert tasks per block
#define EBLK (BB / TPB)  // 512 expert blocks

// inter-kernel scratch
__device__ float g_select[BB * EE];
__device__ float g_gate[BB];
__device__ int   g_index[BB];
__device__ int   g_order[BB];                       // b's sorted by expert
__device__ unsigned int g_ticket;                   // self-resetting
__device__ __align__(16) __nv_bfloat16 g_xbf[BB * PP * KK];   // bf16 patches (16 MB)

// ---------------- helpers ----------------
__device__ __forceinline__ uint32_t smem_u32(const void* p) {
    uint32_t a;
    asm("{ .reg .u64 t; cvta.to.shared.u64 t, %1; cvt.u32.u64 %0, t; }" : "=r"(a) : "l"(p));
    return a;
}

__device__ __forceinline__ void ldsm_x4(uint32_t& r0, uint32_t& r1, uint32_t& r2, uint32_t& r3,
                                        uint32_t addr) {
    asm volatile("ldmatrix.sync.aligned.m8n8.x4.shared.b16 {%0,%1,%2,%3}, [%4];"
                 : "=r"(r0), "=r"(r1), "=r"(r2), "=r"(r3) : "r"(addr));
}

__device__ __forceinline__ void mma_bf16(float* d, const uint32_t* a, uint32_t b0, uint32_t b1) {
    asm volatile(
        "mma.sync.aligned.m16n8k16.row.col.f32.bf16.bf16.f32 "
        "{%0,%1,%2,%3}, {%4,%5,%6,%7}, {%8,%9}, {%0,%1,%2,%3};"
        : "+f"(d[0]), "+f"(d[1]), "+f"(d[2]), "+f"(d[3])
        : "r"(a[0]), "r"(a[1]), "r"(a[2]), "r"(a[3]), "r"(b0), "r"(b1));
}

__device__ __forceinline__ uint32_t pack_bf16x2(float lo, float hi) {
    __nv_bfloat162 h = __float22bfloat162_rn(make_float2(lo, hi));
    return *(uint32_t*)&h;
}

__device__ __forceinline__ void cp_async16(uint32_t smem_addr, const void* gmem) {
    asm volatile("cp.async.cg.shared.global [%0], [%1], 16;" :: "r"(smem_addr), "l"(gmem));
}

// ---------------------------------------------------------------------------
// K1: router (+ compaction & loss in last block). Writes bf16 patches to g_xbf.
// 1024 blocks x 256 threads; 2 b's per block, 4 warps per b.  (unchanged)
// ---------------------------------------------------------------------------
__global__ __launch_bounds__(256) void router_kernel(
    const float* __restrict__ x,
    const float* __restrict__ rw,
    float* __restrict__ out,
    int full)
{
    __shared__ float4 sacc[8][16];
    __shared__ int    s_last;
    __shared__ int    hist[EE];
    __shared__ int    ofs[EE];
    __shared__ float  esum[8][EE];

    const int t = threadIdx.x;
    const int wid = t >> 5, lid = t & 31;
    const int wq = wid & 3;                    // quarter of x[b]
    const int jb = wid >> 2;                   // local b (0..1)
    const int b = blockIdx.x * 2 + jb;

    const float4* xb4 = (const float4*)(x + (size_t)b * DD);
    __nv_bfloat16* xo = g_xbf + (size_t)b * (PP * KK);

    float4 v[8];
    #pragma unroll
    for (int i = 0; i < 8; i++)
        v[i] = xb4[lid + (((wq << 3) + i) << 5)];

    float4 acc = make_float4(0.f, 0.f, 0.f, 0.f);
    const int kq = lid & 15;
    #pragma unroll
    for (int i = 0; i < 8; i++) {
        acc.x += v[i].x; acc.y += v[i].y; acc.z += v[i].z; acc.w += v[i].w;
        const int p = (lid >> 4) + (((wq << 3) + i) << 1);
        uint2 pk;
        pk.x = pack_bf16x2(v[i].x, v[i].y);
        pk.y = pack_bf16x2(v[i].z, v[i].w);
        *(uint2*)(xo + p * KK + (kq << 2)) = pk;
    }
    acc.x += __shfl_xor_sync(0xffffffffu, acc.x, 16);
    acc.y += __shfl_xor_sync(0xffffffffu, acc.y, 16);
    acc.z += __shfl_xor_sync(0xffffffffu, acc.z, 16);
    acc.w += __shfl_xor_sync(0xffffffffu, acc.w, 16);
    if (lid < 16) sacc[wid][lid] = acc;
    __syncthreads();

    if (wq == 0) {
        #pragma unroll
        for (int q = 1; q < 4; q++) {
            float4 o = sacc[wid + q][kq];
            acc.x += o.x; acc.y += o.y; acc.z += o.z; acc.w += o.w;
        }
        const float4* rw4 = (const float4*)rw;
        float sel[EE];
        #pragma unroll
        for (int e = 0; e < EE; e++) {
            float4 w = rw4[e * 16 + kq];
            float p = acc.x * w.x + acc.y * w.y + acc.z * w.z + acc.w * w.w;
            p += __shfl_xor_sync(0xffffffffu, p, 8);
            p += __shfl_xor_sync(0xffffffffu, p, 4);
            p += __shfl_xor_sync(0xffffffffu, p, 2);
            p += __shfl_xor_sync(0xffffffffu, p, 1);
            sel[e] = p;
        }
        float g = sel[0]; int idx = 0;
        #pragma unroll
        for (int e = 1; e < EE; e++) { if (sel[e] > g) { g = sel[e]; idx = e; } }

        if (lid == 0) {
            g_index[b] = idx;
            g_gate[b]  = g;
            float4* s4 = (float4*)(g_select + b * EE);
            s4[0] = make_float4(sel[0], sel[1], sel[2], sel[3]);
            s4[1] = make_float4(sel[4], sel[5], sel[6], sel[7]);
        }
        if (full && lid < EE)
            out[BB * 2 + b * EE + lid] = (lid == idx && g != 0.f) ? 1.f : 0.f;
    }
    __syncthreads();

    if (t == 0) {
        __threadfence();
        unsigned int tk = atomicAdd(&g_ticket, 1u);
        s_last = (tk == RBLK - 1) ? 1 : 0;
    }
    __syncthreads();
    if (!s_last) return;
    __threadfence();

    if (t < EE) hist[t] = 0;
    __syncthreads();

    int idx8[8];
    #pragma unroll
    for (int i = 0; i < 8; i++) {
        idx8[i] = g_index[t + (i << 8)];
        atomicAdd(&hist[idx8[i]], 1);
    }
    __syncthreads();

    if (t == 0) {
        int run = 0;
        #pragma unroll
        for (int e = 0; e < EE; e++) { ofs[e] = run; run += hist[e]; }
    }
    __syncthreads();

    #pragma unroll
    for (int i = 0; i < 8; i++) {
        int pos = atomicAdd(&ofs[idx8[i]], 1);
        g_order[pos] = t + (i << 8);
    }

    float my[EE];
    #pragma unroll
    for (int e = 0; e < EE; e++) my[e] = 0.f;
    #pragma unroll
    for (int i = 0; i < 8; i++) {
        const float4* s4 = (const float4*)(g_select + (t + (i << 8)) * EE);
        float4 v0 = s4[0], v1 = s4[1];
        my[0] += v0.x; my[1] += v0.y; my[2] += v0.z; my[3] += v0.w;
        my[4] += v1.x; my[5] += v1.y; my[6] += v1.z; my[7] += v1.w;
    }
    #pragma unroll
    for (int o = 16; o > 0; o >>= 1)
        #pragma unroll
        for (int e = 0; e < EE; e++)
            my[e] += __shfl_xor_sync(0xffffffffu, my[e], o);
    if (lid == 0) {
        #pragma unroll
        for (int e = 0; e < EE; e++) esum[wid][e] = my[e];
    }
    __syncthreads();

    if (t == 0) {
        if (full) {
            float L = 0.f;
            #pragma unroll
            for (int e = 0; e < EE; e++) {
                float S = 0.f;
                #pragma unroll
                for (int w = 0; w < 8; w++) S += esum[w][e];
                L += S * (float)hist[e];
            }
            out[BB * 2 + BB * EE] = L * (float)EE / ((float)BB * (float)BB);
        }
        atomicExch(&g_ticket, 0u);
    }
}

// ---------------------------------------------------------------------------
// K2: expert GEMMs. 512 blocks x 4 sorted tasks. A (weight) fragments cached
// in registers across tasks; per task only B ldsm (8/warp). p processed in two
// halves of 16 to keep accumulators at 16 regs. One syncthreads per task;
// softmax epilogues deferred.
// ---------------------------------------------------------------------------
__global__ __launch_bounds__(256, 3) void expert_kernel(
    const float* __restrict__ ew,
    const float* __restrict__ eb,
    float* __restrict__ out)
{
    __shared__ __align__(16) __nv_bfloat16 asm_w[TWO_C * WROW];   // A: weights [c][k]
    __shared__ __align__(16) __nv_bfloat16 bsm[3][PP * WROW];     // B: ring of x tiles
    __shared__ float bias_s[TWO_C];
    __shared__ float wred[TPB][8];

    const int t = threadIdx.x;
    const int wid = t >> 5, lid = t & 31;
    const int cw = wid & 3;
    const int pw = wid >> 2;
    const uint32_t Abase = smem_u32(asm_w);
    const uint32_t Bbase = smem_u32(bsm);
    const uint32_t a_addr = Abase + (uint32_t)(((cw << 5) + (lid & 15)) * WROWB + ((lid >> 4) << 4));
    const uint32_t b_off  = (uint32_t)(((pw << 5) + (lid & 7) + ((lid >> 4) << 3)) * WROWB
                                       + (((lid >> 3) & 1) << 4));
    const int ch0 = t, ch1 = t + 256;
    const uint32_t d0 = (uint32_t)((ch0 >> 3) * WROWB + ((ch0 & 7) << 4));
    const uint32_t d1 = (uint32_t)((ch1 >> 3) * WROWB + ((ch1 & 7) << 4));

    int bs[TPB], es[TPB];
    #pragma unroll
    for (int i = 0; i < TPB; i++) {
        bs[i] = __ldg(&g_order[blockIdx.x * TPB + i]);
        es[i] = __ldg(&g_index[bs[i]]);
    }

    // prefetch B tiles for tasks 0 and 1 into ring slots 0, 1
    #pragma unroll
    for (int pfi = 0; pfi < 2; pfi++) {
        const char* src = (const char*)(g_xbf + (size_t)bs[pfi] * (PP * KK));
        uint32_t dst = Bbase + pfi * BUFB;
        cp_async16(dst + d0, src + (ch0 << 4));
        cp_async16(dst + d1, src + (ch1 << 4));
        asm volatile("cp.async.commit_group;" ::: "memory");
    }

    // stage weights for first expert, then load A fragments into registers
    uint32_t Af[4][8];       // [ks][a0:0..3, a1:4..7]
    int e_cur = es[0];
    {
        const float4* src = (const float4*)(ew + (size_t)e_cur * (TWO_C * KK));
        #pragma unroll
        for (int i = 0; i < 8; i++) {
            int idx4 = (i << 8) + t;
            float4 v = src[idx4];
            uint2 pk;
            pk.x = pack_bf16x2(v.x, v.y);
            pk.y = pack_bf16x2(v.z, v.w);
            *(uint2*)&asm_w[(idx4 >> 4) * WROW + ((idx4 & 15) << 2)] = pk;
        }
        if (t < TWO_C) bias_s[t] = eb[e_cur * TWO_C + t];
    }
    __syncthreads();
    #pragma unroll
    for (int ks = 0; ks < 4; ks++) {
        ldsm_x4(Af[ks][0], Af[ks][1], Af[ks][2], Af[ks][3], a_addr + ks * 32);
        ldsm_x4(Af[ks][4], Af[ks][5], Af[ks][6], Af[ks][7], a_addr + 16 * WROWB + ks * 32);
    }

    #pragma unroll
    for (int it = 0; it < TPB; it++) {
        // B tile for task `it` ready (groups retire in commit order)
        if (it < TPB - 1) {
            asm volatile("cp.async.wait_group 1;" ::: "memory");
        } else {
            asm volatile("cp.async.wait_group 0;" ::: "memory");
        }
        __syncthreads();   // tile visible; ring slot (it+2)%3 free

        // prefetch task it+2 into ring slot (it+2)%3
        if (it < TPB - 2) {
            const char* src = (const char*)(g_xbf + (size_t)bs[it + 2] * (PP * KK));
            uint32_t dst = Bbase + (uint32_t)(((it + 2) % 3) * BUFB);
            cp_async16(dst + d0, src + (ch0 << 4));
            cp_async16(dst + d1, src + (ch1 << 4));
            asm volatile("cp.async.commit_group;" ::: "memory");
        }

        // rare (block-uniform): restage weights + refresh A fragments
        if (es[it] != e_cur) {
            e_cur = es[it];
            const float4* src = (const float4*)(ew + (size_t)e_cur * (TWO_C * KK));
            #pragma unroll
            for (int i = 0; i < 8; i++) {
                int idx4 = (i << 8) + t;
                float4 v = src[idx4];
                uint2 pk;
                pk.x = pack_bf16x2(v.x, v.y);
                pk.y = pack_bf16x2(v.z, v.w);
                *(uint2*)&asm_w[(idx4 >> 4) * WROW + ((idx4 & 15) << 2)] = pk;
            }
            if (t < TWO_C) bias_s[t] = eb[e_cur * TWO_C + t];
            __syncthreads();
            #pragma unroll
            for (int ks = 0; ks < 4; ks++) {
                ldsm_x4(Af[ks][0], Af[ks][1], Af[ks][2], Af[ks][3], a_addr + ks * 32);
                ldsm_x4(Af[ks][4], Af[ks][5], Af[ks][6], Af[ks][7], a_addr + 16 * WROWB + ks * 32);
            }
        }

        // ---- GEMM from ring slot it%3, two p-halves of 16 (accv = 16 regs)
        const uint32_t b_base = Bbase + (uint32_t)((it % 3) * BUFB) + b_off;
        float part = 0.f;

        #pragma unroll
        for (int h = 0; h < 2; h++) {
            float accv[2][2][4];
            #pragma unroll
            for (int m = 0; m < 2; m++)
                #pragma unroll
                for (int n = 0; n < 2; n++)
                    #pragma unroll
                    for (int i = 0; i < 4; i++) accv[m][n][i] = 0.f;

            #pragma unroll
            for (int ks = 0; ks < 4; ks++) {
                uint32_t r0, r1, r2, r3;
                ldsm_x4(r0, r1, r2, r3, b_base + h * (16 * WROWB) + ks * 32);
                mma_bf16(accv[0][0], &Af[ks][0], r0, r1);
                mma_bf16(accv[0][1], &Af[ks][0], r2, r3);
                mma_bf16(accv[1][0], &Af[ks][4], r0, r1);
                mma_bf16(accv[1][1], &Af[ks][4], r2, r3);
            }

            #pragma unroll
            for (int m = 0; m < 2; m++) {
                const float bv1 = bias_s[(cw << 5) + (m << 4) + (lid >> 2)];
                const float bv2 = bias_s[(cw << 5) + (m << 4) + (lid >> 2) + 8];
                #pragma unroll
                for (int n = 0; n < 2; n++) {
                    float z0 = accv[m][n][0] + bv1;
                    float z1 = accv[m][n][1] + bv1;
                    float z2 = accv[m][n][2] + bv2;
                    float z3 = accv[m][n][3] + bv2;
                    part += z0 * z0 * z0 + z1 * z1 * z1 + z2 * z2 * z2 + z3 * z3 * z3;
                }
            }
        }

        #pragma unroll
        for (int o = 16; o > 0; o >>= 1)
            part += __shfl_xor_sync(0xffffffffu, part, o);
        if (lid == 0) wred[it][wid] = part;
    }

    __syncthreads();

    // ---- all four softmaxes in parallel (threads 0..3)
    if (t < TPB) {
        float v0 = wred[t][0] + wred[t][1] + wred[t][4] + wred[t][5];   // c in [0,64)
        float v1 = wred[t][2] + wred[t][3] + wred[t][6] + wred[t][7];   // c in [64,128)
        float gate = __ldg(&g_gate[bs[t]]);
        float a0v = gate * v0, a1v = gate * v1;
        float m  = fmaxf(a0v, a1v);
        float e0 = expf(a0v - m), e1 = expf(a1v - m);
        float inv = 1.f / (e0 + e1);
        out[bs[t] * 2 + 0] = e0 * inv;
        out[bs[t] * 2 + 1] = e1 * inv;
    }
}

// ---------------------------------------------------------------------------
extern "C" void kernel_launch(void* const* d_in, const int* in_sizes, int n_in,
                              void* d_out, int out_size)
{
    const float* x  = (const float*)d_in[0];
    const float* rw = (const float*)d_in[1];
    const float* ew = (const float*)d_in[2];
    const float* eb = (const float*)d_in[3];
    float* out = (float*)d_out;

    const int full = (out_size >= BB * 2 + BB * EE + 1) ? 1 : 0;

    router_kernel<<<RBLK, 256>>>(x, rw, out, full);
    expert_kernel<<<EBLK, 256>>>(ew, eb, out);
}

// round 11
// speedup vs baseline: 1.0862x; 1.0862x over previous
#include <cuda_runtime.h>
#include <cuda_bf16.h>
#include <cstdint>
#include <math.h>

// Problem constants
#define BB 2048
#define DD 4096
#define PP 64
#define EE 8
#define KK 64
#define TWO_C 128

#define WROW 72               // padded row stride in bf16 (144 B)
#define WROWB 144
#define BUFB (PP * WROWB)     // one B tile: 9216 B

#define TPB 4                 // batch elements per block
#define NBLK (BB / TPB)       // 512 blocks

// dynamic smem layout
#define SM_A 0                          // A tile: 18432 B
#define SM_B 18432                      // 4 B tiles: 36864 B
#define SM_TOTAL (18432 + TPB * BUFB)   // 55296 B

// loss accumulators (deterministic fixed-point; self-resetting per launch)
__device__ unsigned long long g_lsum[EE];
__device__ int                g_cnt[EE];
__device__ unsigned int       g_ticket;

// ---------------- helpers ----------------
__device__ __forceinline__ uint32_t smem_u32(const void* p) {
    uint32_t a;
    asm("{ .reg .u64 t; cvta.to.shared.u64 t, %1; cvt.u32.u64 %0, t; }" : "=r"(a) : "l"(p));
    return a;
}
__device__ __forceinline__ void ldsm_x4(uint32_t& r0, uint32_t& r1, uint32_t& r2, uint32_t& r3,
                                        uint32_t addr) {
    asm volatile("ldmatrix.sync.aligned.m8n8.x4.shared.b16 {%0,%1,%2,%3}, [%4];"
                 : "=r"(r0), "=r"(r1), "=r"(r2), "=r"(r3) : "r"(addr));
}
__device__ __forceinline__ void mma_bf16(float* d, const uint32_t* a, uint32_t b0, uint32_t b1) {
    asm volatile(
        "mma.sync.aligned.m16n8k16.row.col.f32.bf16.bf16.f32 "
        "{%0,%1,%2,%3}, {%4,%5,%6,%7}, {%8,%9}, {%0,%1,%2,%3};"
        : "+f"(d[0]), "+f"(d[1]), "+f"(d[2]), "+f"(d[3])
        : "r"(a[0]), "r"(a[1]), "r"(a[2]), "r"(a[3]), "r"(b0), "r"(b1));
}
__device__ __forceinline__ uint32_t pack_bf16x2(float lo, float hi) {
    __nv_bfloat162 h = __float22bfloat162_rn(make_float2(lo, hi));
    return *(uint32_t*)&h;
}
__device__ __forceinline__ void cmpswap(int& a, int& b) {
    int lo = min(a, b), hi = max(a, b);
    a = lo; b = hi;
}

// ---------------------------------------------------------------------------
// ONE fused kernel. Block = 4 batch elements, 256 threads (8 warps).
//  phase 1: each warp-pair loads one x[b] (DRAM, once), fp32 k-sums + bf16 tile
//  phase 2: 4 exact-fp32 routers (warps 0,2,4,6); loss atomics; one-hot
//  phase 3: sort 4 tasks by expert (network); GEMM+cube per task with
//           register-cached A fragments; weights staged from L2 per distinct expert
//  phase 4: 4 parallel softmaxes; last block finalizes loss
// ---------------------------------------------------------------------------
__global__ __launch_bounds__(256, 3) void moe_one(
    const float* __restrict__ x,
    const float* __restrict__ rw,
    const float* __restrict__ ew,
    const float* __restrict__ eb,
    float* __restrict__ out,
    int full)
{
    extern __shared__ __align__(16) char dsm[];
    __nv_bfloat16* asm_w = (__nv_bfloat16*)(dsm + SM_A);
    __nv_bfloat16* bsm   = (__nv_bfloat16*)(dsm + SM_B);

    __shared__ float4 sacc[TPB][16];
    __shared__ float  bias_s[TWO_C];
    __shared__ float  wred[TPB][8];
    __shared__ int    s_idx[TPB];
    __shared__ float  s_gate[TPB];

    const int t = threadIdx.x;
    const int wid = t >> 5, lid = t & 31;
    const int jb = wid >> 1;          // local b (0..3), one warp-pair each
    const int h  = wid & 1;           // which half of x[b]
    const int b  = blockIdx.x * TPB + jb;

    // ---- phase 1: load x[b] half, fp32 k-group partials + bf16 smem tile
    const float4* xb4 = (const float4*)(x + (size_t)b * DD);
    __nv_bfloat16* myb = bsm + jb * (PP * WROW);
    float4 acc = make_float4(0.f, 0.f, 0.f, 0.f);
    const int kq = lid & 15;

    #pragma unroll
    for (int ch = 0; ch < 2; ch++) {
        float4 v[8];
        #pragma unroll
        for (int i = 0; i < 8; i++)
            v[i] = xb4[lid + ((ch * 8 + i) << 5) + (h << 9)];
        #pragma unroll
        for (int i = 0; i < 8; i++) {
            acc.x += v[i].x; acc.y += v[i].y; acc.z += v[i].z; acc.w += v[i].w;
            const int p = (lid >> 4) + ((ch * 8 + i) << 1) + (h << 5);
            uint2 pk;
            pk.x = pack_bf16x2(v[i].x, v[i].y);
            pk.y = pack_bf16x2(v[i].z, v[i].w);
            *(uint2*)(myb + p * WROW + (kq << 2)) = pk;
        }
    }
    acc.x += __shfl_xor_sync(0xffffffffu, acc.x, 16);
    acc.y += __shfl_xor_sync(0xffffffffu, acc.y, 16);
    acc.z += __shfl_xor_sync(0xffffffffu, acc.z, 16);
    acc.w += __shfl_xor_sync(0xffffffffu, acc.w, 16);
    if (h == 1 && lid < 16) sacc[jb][lid] = acc;
    __syncthreads();                                    // S1: tiles + partials ready

    // ---- phase 2: routers on warps 0,2,4,6 (h==0), one per b
    if (h == 0) {
        float4 o = sacc[jb][kq];
        acc.x += o.x; acc.y += o.y; acc.z += o.z; acc.w += o.w;

        const float4* rw4 = (const float4*)rw;
        float mysel = 0.f;                 // lane e keeps sel[e]
        float g = -1e30f; int idx = 0;
        #pragma unroll
        for (int e = 0; e < EE; e++) {
            float4 w = rw4[e * 16 + kq];
            float p = acc.x * w.x + acc.y * w.y + acc.z * w.z + acc.w * w.w;
            p += __shfl_xor_sync(0xffffffffu, p, 8);
            p += __shfl_xor_sync(0xffffffffu, p, 4);
            p += __shfl_xor_sync(0xffffffffu, p, 2);
            p += __shfl_xor_sync(0xffffffffu, p, 1);
            if (lid == e) mysel = p;
            if (p > g) { g = p; idx = e; }
        }
        if (lid == 0) {
            s_idx[jb] = idx; s_gate[jb] = g;
            atomicAdd(&g_cnt[idx], 1);
        }
        if (lid < EE) {
            long long q = llrint((double)mysel * 4294967296.0);
            atomicAdd(&g_lsum[lid], (unsigned long long)q);
            if (full)
                out[BB * 2 + b * EE + lid] = (lid == idx && g != 0.f) ? 1.f : 0.f;
        }
    }
    __syncthreads();                                    // S2: routing visible

    // ---- phase 3: sort 4 tasks by expert (key = e*4 + tile; distinct)
    int k0 = s_idx[0] * 4 + 0, k1 = s_idx[1] * 4 + 1,
        k2 = s_idx[2] * 4 + 2, k3 = s_idx[3] * 4 + 3;
    cmpswap(k0, k1); cmpswap(k2, k3); cmpswap(k0, k2); cmpswap(k1, k3); cmpswap(k1, k2);

    const int cw = wid & 3;
    const int pw = wid >> 2;
    const uint32_t Abase = smem_u32(asm_w);
    const uint32_t Bbase = smem_u32(bsm);
    const uint32_t a_addr = Abase + (uint32_t)(((cw << 5) + (lid & 15)) * WROWB + ((lid >> 4) << 4));
    const uint32_t b_off  = (uint32_t)(((pw << 5) + (lid & 7) + ((lid >> 4) << 3)) * WROWB
                                       + (((lid >> 3) & 1) << 4));

    uint32_t Af[4][8];
    int e_cur = -1;

    #pragma unroll
    for (int it = 0; it < TPB; it++) {
        const int key  = (it == 0) ? k0 : (it == 1) ? k1 : (it == 2) ? k2 : k3;
        const int e    = key >> 2;
        const int tile = key & 3;

        if (e != e_cur) {                                // block-uniform
            if (e_cur >= 0) __syncthreads();             // protect old asm_w reads
            e_cur = e;
            const float4* src = (const float4*)(ew + (size_t)e * (TWO_C * KK));
            #pragma unroll
            for (int i = 0; i < 8; i++) {
                int idx4 = (i << 8) + t;                 // row = idx4>>4, ch = idx4&15
                float4 v = src[idx4];
                uint2 pk;
                pk.x = pack_bf16x2(v.x, v.y);
                pk.y = pack_bf16x2(v.z, v.w);
                *(uint2*)&asm_w[(idx4 >> 4) * WROW + ((idx4 & 15) << 2)] = pk;
            }
            if (t < TWO_C) bias_s[t] = eb[e * TWO_C + t];
            __syncthreads();
            #pragma unroll
            for (int ks = 0; ks < 4; ks++) {
                ldsm_x4(Af[ks][0], Af[ks][1], Af[ks][2], Af[ks][3], a_addr + ks * 32);
                ldsm_x4(Af[ks][4], Af[ks][5], Af[ks][6], Af[ks][7], a_addr + 16 * WROWB + ks * 32);
            }
        }

        // ---- GEMM on tile, two p-halves of 16
        const uint32_t b_base = Bbase + (uint32_t)(tile * BUFB) + b_off;
        float part = 0.f;
        #pragma unroll
        for (int hh = 0; hh < 2; hh++) {
            float accv[2][2][4];
            #pragma unroll
            for (int m = 0; m < 2; m++)
                #pragma unroll
                for (int n = 0; n < 2; n++)
                    #pragma unroll
                    for (int i = 0; i < 4; i++) accv[m][n][i] = 0.f;

            #pragma unroll
            for (int ks = 0; ks < 4; ks++) {
                uint32_t r0, r1, r2, r3;
                ldsm_x4(r0, r1, r2, r3, b_base + hh * (16 * WROWB) + ks * 32);
                mma_bf16(accv[0][0], &Af[ks][0], r0, r1);
                mma_bf16(accv[0][1], &Af[ks][0], r2, r3);
                mma_bf16(accv[1][0], &Af[ks][4], r0, r1);
                mma_bf16(accv[1][1], &Af[ks][4], r2, r3);
            }

            #pragma unroll
            for (int m = 0; m < 2; m++) {
                const float bv1 = bias_s[(cw << 5) + (m << 4) + (lid >> 2)];
                const float bv2 = bias_s[(cw << 5) + (m << 4) + (lid >> 2) + 8];
                #pragma unroll
                for (int n = 0; n < 2; n++) {
                    float z0 = accv[m][n][0] + bv1;
                    float z1 = accv[m][n][1] + bv1;
                    float z2 = accv[m][n][2] + bv2;
                    float z3 = accv[m][n][3] + bv2;
                    part += z0 * z0 * z0 + z1 * z1 * z1 + z2 * z2 * z2 + z3 * z3 * z3;
                }
            }
        }
        #pragma unroll
        for (int o = 16; o > 0; o >>= 1)
            part += __shfl_xor_sync(0xffffffffu, part, o);
        if (lid == 0) wred[it][wid] = part;
    }

    __syncthreads();                                    // S-final

    // ---- phase 4: 4 softmaxes in parallel
    if (t < TPB) {
        const int key  = (t == 0) ? k0 : (t == 1) ? k1 : (t == 2) ? k2 : k3;
        const int tile = key & 3;
        float v0 = wred[t][0] + wred[t][1] + wred[t][4] + wred[t][5];   // c in [0,64)
        float v1 = wred[t][2] + wred[t][3] + wred[t][6] + wred[t][7];   // c in [64,128)
        float gate = s_gate[tile];
        float a0v = gate * v0, a1v = gate * v1;
        float m  = fmaxf(a0v, a1v);
        float e0 = expf(a0v - m), e1 = expf(a1v - m);
        float inv = 1.f / (e0 + e1);
        const int bo = blockIdx.x * TPB + tile;
        out[bo * 2 + 0] = e0 * inv;
        out[bo * 2 + 1] = e1 * inv;
    }

    // ---- loss finalization (last block), off everyone else's path
    if (t == 32) {
        __threadfence();
        unsigned int tk = atomicAdd(&g_ticket, 1u);
        if (tk == NBLK - 1) {
            __threadfence();
            double L = 0.0;
            #pragma unroll
            for (int e = 0; e < EE; e++) {
                unsigned long long sraw = atomicAdd(&g_lsum[e], 0ULL);
                int cc = atomicAdd(&g_cnt[e], 0);
                L += ((double)(long long)sraw * (1.0 / 4294967296.0)) * (double)cc;
            }
            if (full)
                out[BB * 2 + BB * EE] = (float)(L * (double)EE / ((double)BB * (double)BB));
            #pragma unroll
            for (int e = 0; e < EE; e++) {
                atomicExch(&g_lsum[e], 0ULL);
                atomicExch(&g_cnt[e], 0);
            }
            atomicExch(&g_ticket, 0u);
        }
    }
}

// ---------------------------------------------------------------------------
extern "C" void kernel_launch(void* const* d_in, const int* in_sizes, int n_in,
                              void* d_out, int out_size)
{
    const float* x  = (const float*)d_in[0];
    const float* rw = (const float*)d_in[1];
    const float* ew = (const float*)d_in[2];
    const float* eb = (const float*)d_in[3];
    float* out = (float*)d_out;

    const int full = (out_size >= BB * 2 + BB * EE + 1) ? 1 : 0;

    cudaFuncSetAttribute(moe_one, cudaFuncAttributeMaxDynamicSharedMemorySize, SM_TOTAL);
    moe_one<<<NBLK, 256, SM_TOTAL>>>(x, rw, ew, eb, out, full);
}

// round 12
// speedup vs baseline: 1.1948x; 1.1000x over previous
#include <cuda_runtime.h>
#include <cuda_bf16.h>
#include <cstdint>
#include <math.h>

// Problem constants
#define BB 2048
#define DD 4096
#define PP 64
#define EE 8
#define KK 64
#define TWO_C 128

#define WROW 72               // padded row stride in bf16 (144 B)
#define WROWB 144
#define BUFB (PP * WROWB)     // one B tile: 9216 B

#define TPB 4                 // batch elements per block
#define NBLK (BB / TPB)       // 512 blocks

// dynamic smem layout
#define SM_A    0                        // A tile: 18432 B (aliased w/ sacc pre-GEMM)
#define SM_B    18432                    // 4 B tiles: 36864 B
#define SM_BIAS (18432 + TPB * BUFB)     // 128 floats: 512 B
#define SM_TOTAL (SM_BIAS + 512)         // 55808 B

// loss accumulators (deterministic fixed-point; self-resetting per launch)
__device__ unsigned long long g_lsum[EE];
__device__ int                g_cnt[EE];
__device__ unsigned int       g_ticket;

// ---------------- helpers ----------------
__device__ __forceinline__ uint32_t smem_u32(const void* p) {
    uint32_t a;
    asm("{ .reg .u64 t; cvta.to.shared.u64 t, %1; cvt.u32.u64 %0, t; }" : "=r"(a) : "l"(p));
    return a;
}
__device__ __forceinline__ void ldsm_x4(uint32_t& r0, uint32_t& r1, uint32_t& r2, uint32_t& r3,
                                        uint32_t addr) {
    asm volatile("ldmatrix.sync.aligned.m8n8.x4.shared.b16 {%0,%1,%2,%3}, [%4];"
                 : "=r"(r0), "=r"(r1), "=r"(r2), "=r"(r3) : "r"(addr));
}
__device__ __forceinline__ void mma_bf16(float* d, const uint32_t* a, uint32_t b0, uint32_t b1) {
    asm volatile(
        "mma.sync.aligned.m16n8k16.row.col.f32.bf16.bf16.f32 "
        "{%0,%1,%2,%3}, {%4,%5,%6,%7}, {%8,%9}, {%0,%1,%2,%3};"
        : "+f"(d[0]), "+f"(d[1]), "+f"(d[2]), "+f"(d[3])
        : "r"(a[0]), "r"(a[1]), "r"(a[2]), "r"(a[3]), "r"(b0), "r"(b1));
}
__device__ __forceinline__ uint32_t pack_bf16x2(float lo, float hi) {
    __nv_bfloat162 h = __float22bfloat162_rn(make_float2(lo, hi));
    return *(uint32_t*)&h;
}
__device__ __forceinline__ void cmpswap(int& a, int& b) {
    int lo = min(a, b), hi = max(a, b);
    a = lo; b = hi;
}

// ---------------------------------------------------------------------------
// ONE fused kernel. Block = 4 batch elements, 256 threads, 4 blocks/SM.
// ---------------------------------------------------------------------------
__global__ __launch_bounds__(256, 4) void moe_one(
    const float* __restrict__ x,
    const float* __restrict__ rw,
    const float* __restrict__ ew,
    const float* __restrict__ eb,
    float* __restrict__ out,
    int full)
{
    extern __shared__ __align__(16) char dsm[];
    __nv_bfloat16* asm_w = (__nv_bfloat16*)(dsm + SM_A);
    __nv_bfloat16* bsm   = (__nv_bfloat16*)(dsm + SM_B);
    float* bias_s        = (float*)(dsm + SM_BIAS);
    float4 (*sacc)[16]   = (float4(*)[16])(dsm + SM_A);   // alias: dead before weights staged

    __shared__ float  wred[TPB][8];
    __shared__ int    s_idx[TPB];
    __shared__ float  s_gate[TPB];

    const int t = threadIdx.x;
    const int wid = t >> 5, lid = t & 31;
    const int jb = wid >> 1;          // local b (0..3), one warp-pair each
    const int h  = wid & 1;           // which half of x[b]
    const int b  = blockIdx.x * TPB + jb;

    // ---- phase 1: load x[b] half (4 batches of 4 float4), fp32 partials + bf16 tile
    const float4* xb4 = (const float4*)(x + (size_t)b * DD);
    __nv_bfloat16* myb = bsm + jb * (PP * WROW);
    float4 acc = make_float4(0.f, 0.f, 0.f, 0.f);
    const int kq = lid & 15;

    #pragma unroll
    for (int ch = 0; ch < 4; ch++) {
        float4 v[4];
        #pragma unroll
        for (int i = 0; i < 4; i++)
            v[i] = xb4[lid + ((ch * 4 + i) << 5) + (h << 9)];
        #pragma unroll
        for (int i = 0; i < 4; i++) {
            acc.x += v[i].x; acc.y += v[i].y; acc.z += v[i].z; acc.w += v[i].w;
            const int p = (lid >> 4) + ((ch * 4 + i) << 1) + (h << 5);
            uint2 pk;
            pk.x = pack_bf16x2(v[i].x, v[i].y);
            pk.y = pack_bf16x2(v[i].z, v[i].w);
            *(uint2*)(myb + p * WROW + (kq << 2)) = pk;
        }
    }
    acc.x += __shfl_xor_sync(0xffffffffu, acc.x, 16);
    acc.y += __shfl_xor_sync(0xffffffffu, acc.y, 16);
    acc.z += __shfl_xor_sync(0xffffffffu, acc.z, 16);
    acc.w += __shfl_xor_sync(0xffffffffu, acc.w, 16);
    if (h == 1 && lid < 16) sacc[jb][lid] = acc;
    __syncthreads();                                    // S1: tiles + partials ready

    // ---- phase 2: routers on warps 0,2,4,6 (h==0), one per b
    if (h == 0) {
        float4 o = sacc[jb][kq];
        acc.x += o.x; acc.y += o.y; acc.z += o.z; acc.w += o.w;

        const float4* rw4 = (const float4*)rw;
        float mysel = 0.f;                 // lane e keeps sel[e]
        float g = -1e30f; int idx = 0;
        #pragma unroll
        for (int e = 0; e < EE; e++) {
            float4 w = rw4[e * 16 + kq];
            float p = acc.x * w.x + acc.y * w.y + acc.z * w.z + acc.w * w.w;
            p += __shfl_xor_sync(0xffffffffu, p, 8);
            p += __shfl_xor_sync(0xffffffffu, p, 4);
            p += __shfl_xor_sync(0xffffffffu, p, 2);
            p += __shfl_xor_sync(0xffffffffu, p, 1);
            if (lid == e) mysel = p;
            if (p > g) { g = p; idx = e; }
        }
        if (lid == 0) {
            s_idx[jb] = idx; s_gate[jb] = g;
            atomicAdd(&g_cnt[idx], 1);
        }
        if (lid < EE) {
            long long q = llrint((double)mysel * 4294967296.0);
            atomicAdd(&g_lsum[lid], (unsigned long long)q);
            if (full)
                out[BB * 2 + b * EE + lid] = (lid == idx && g != 0.f) ? 1.f : 0.f;
        }
    }
    __syncthreads();                                    // S2: routing visible; sacc dead

    // ---- phase 3: sort 4 tasks by expert (key = e*4 + tile; distinct)
    int k0 = s_idx[0] * 4 + 0, k1 = s_idx[1] * 4 + 1,
        k2 = s_idx[2] * 4 + 2, k3 = s_idx[3] * 4 + 3;
    cmpswap(k0, k1); cmpswap(k2, k3); cmpswap(k0, k2); cmpswap(k1, k3); cmpswap(k1, k2);

    const int cw = wid & 3;
    const int pw = wid >> 2;
    const uint32_t Abase = smem_u32(asm_w);
    const uint32_t Bbase = smem_u32(bsm);
    const uint32_t a_addr = Abase + (uint32_t)(((cw << 5) + (lid & 15)) * WROWB + ((lid >> 4) << 4));
    const uint32_t b_off  = (uint32_t)(((pw << 5) + (lid & 7) + ((lid >> 4) << 3)) * WROWB
                                       + (((lid >> 3) & 1) << 4));
    int e_cur = -1;

    #pragma unroll
    for (int it = 0; it < TPB; it++) {
        const int key  = (it == 0) ? k0 : (it == 1) ? k1 : (it == 2) ? k2 : k3;
        const int e    = key >> 2;
        const int tile = key & 3;

        if (e != e_cur) {                                // block-uniform
            if (e_cur >= 0) __syncthreads();             // protect old asm_w reads
            e_cur = e;
            const float4* src = (const float4*)(ew + (size_t)e * (TWO_C * KK));
            #pragma unroll
            for (int i = 0; i < 8; i++) {
                int idx4 = (i << 8) + t;                 // row = idx4>>4, ch = idx4&15
                float4 v = src[idx4];
                uint2 pk;
                pk.x = pack_bf16x2(v.x, v.y);
                pk.y = pack_bf16x2(v.z, v.w);
                *(uint2*)&asm_w[(idx4 >> 4) * WROW + ((idx4 & 15) << 2)] = pk;
            }
            if (t < TWO_C) bias_s[t] = eb[e * TWO_C + t];
            __syncthreads();
        }

        // ---- GEMM on tile, two p-halves of 16; A+B fragments loaded per ks
        const uint32_t b_base = Bbase + (uint32_t)(tile * BUFB) + b_off;
        float part = 0.f;
        #pragma unroll
        for (int hh = 0; hh < 2; hh++) {
            float accv[2][2][4];
            #pragma unroll
            for (int m = 0; m < 2; m++)
                #pragma unroll
                for (int n = 0; n < 2; n++)
                    #pragma unroll
                    for (int i = 0; i < 4; i++) accv[m][n][i] = 0.f;

            #pragma unroll
            for (int ks = 0; ks < 4; ks++) {
                uint32_t a0[4], a1[4];
                ldsm_x4(a0[0], a0[1], a0[2], a0[3], a_addr + ks * 32);
                ldsm_x4(a1[0], a1[1], a1[2], a1[3], a_addr + 16 * WROWB + ks * 32);
                uint32_t r0, r1, r2, r3;
                ldsm_x4(r0, r1, r2, r3, b_base + hh * (16 * WROWB) + ks * 32);
                mma_bf16(accv[0][0], a0, r0, r1);
                mma_bf16(accv[0][1], a0, r2, r3);
                mma_bf16(accv[1][0], a1, r0, r1);
                mma_bf16(accv[1][1], a1, r2, r3);
            }

            #pragma unroll
            for (int m = 0; m < 2; m++) {
                const float bv1 = bias_s[(cw << 5) + (m << 4) + (lid >> 2)];
                const float bv2 = bias_s[(cw << 5) + (m << 4) + (lid >> 2) + 8];
                #pragma unroll
                for (int n = 0; n < 2; n++) {
                    float z0 = accv[m][n][0] + bv1;
                    float z1 = accv[m][n][1] + bv1;
                    float z2 = accv[m][n][2] + bv2;
                    float z3 = accv[m][n][3] + bv2;
                    part += z0 * z0 * z0 + z1 * z1 * z1 + z2 * z2 * z2 + z3 * z3 * z3;
                }
            }
        }
        #pragma unroll
        for (int o = 16; o > 0; o >>= 1)
            part += __shfl_xor_sync(0xffffffffu, part, o);
        if (lid == 0) wred[it][wid] = part;
    }

    __syncthreads();                                    // S-final

    // ---- phase 4: 4 softmaxes in parallel
    if (t < TPB) {
        const int key  = (t == 0) ? k0 : (t == 1) ? k1 : (t == 2) ? k2 : k3;
        const int tile = key & 3;
        float v0 = wred[t][0] + wred[t][1] + wred[t][4] + wred[t][5];   // c in [0,64)
        float v1 = wred[t][2] + wred[t][3] + wred[t][6] + wred[t][7];   // c in [64,128)
        float gate = s_gate[tile];
        float a0v = gate * v0, a1v = gate * v1;
        float m  = fmaxf(a0v, a1v);
        float e0 = expf(a0v - m), e1 = expf(a1v - m);
        float inv = 1.f / (e0 + e1);
        const int bo = blockIdx.x * TPB + tile;
        out[bo * 2 + 0] = e0 * inv;
        out[bo * 2 + 1] = e1 * inv;
    }

    // ---- loss finalization (last block), off everyone else's path
    if (t == 32) {
        __threadfence();
        unsigned int tk = atomicAdd(&g_ticket, 1u);
        if (tk == NBLK - 1) {
            __threadfence();
            double L = 0.0;
            #pragma unroll
            for (int e = 0; e < EE; e++) {
                unsigned long long sraw = atomicAdd(&g_lsum[e], 0ULL);
                int cc = atomicAdd(&g_cnt[e], 0);
                L += ((double)(long long)sraw * (1.0 / 4294967296.0)) * (double)cc;
            }
            if (full)
                out[BB * 2 + BB * EE] = (float)(L * (double)EE / ((double)BB * (double)BB));
            #pragma unroll
            for (int e = 0; e < EE; e++) {
                atomicExch(&g_lsum[e], 0ULL);
                atomicExch(&g_cnt[e], 0);
            }
            atomicExch(&g_ticket, 0u);
        }
    }
}

// ---------------------------------------------------------------------------
extern "C" void kernel_launch(void* const* d_in, const int* in_sizes, int n_in,
                              void* d_out, int out_size)
{
    const float* x  = (const float*)d_in[0];
    const float* rw = (const float*)d_in[1];
    const float* ew = (const float*)d_in[2];
    const float* eb = (const float*)d_in[3];
    float* out = (float*)d_out;

    const int full = (out_size >= BB * 2 + BB * EE + 1) ? 1 : 0;

    cudaFuncSetAttribute(moe_one, cudaFuncAttributeMaxDynamicSharedMemorySize, SM_TOTAL);
    moe_one<<<NBLK, 256, SM_TOTAL>>>(x, rw, ew, eb, out, full);
}